// round 2
// baseline (speedup 1.0000x reference)
#include <cuda_runtime.h>
#include <math.h>

#define EPSf 1e-6f

// ---- shared memory layout (float offsets) ----
#define S1O   0        // s1R[i*101+d]   (10100)
#define S2O   10100    // s2R[j*101+d]   (10100)
#define CMO   20200    // cosm[i*101+j]  (10100)
#define ATO   30300    // att[i*101+d]   (10100)
#define WFO   40400    // w_full^2  [p*100+d] (1000)
#define WMO   41400    // w_maxpool^2
#define WEO   42400    // w_mean^2
#define WSO   43400    // w_slot4^2 (w7 fwd / w8 bwd)
#define R1WO  44400    // 1/n1w maxpool [i*10+p] (1000)
#define R2WO  45400    // 1/n2w maxpool [j*10+p] (1000)
#define R1O   46400    // 1/||s1_i||  (100)
#define R2O   46500    // 1/||s2_j||  (100)
#define RSO   46600    // rowsum of cosm per i (100)
#define JMO   46700    // argmax j per i (int) (100)
#define R2FO  46800    // 1/||s2_last * w_full_p|| per p (16)
#define MPO   46816    // maxpool partial max scratch [i*25+tx] (2500)
#define SMEM_FLOATS 49320

__device__ __forceinline__ float invs(float x) {
    return 1.0f / sqrtf(fmaxf(x, EPSf));
}

__global__ __launch_bounds__(256, 1) void matching_kernel(
    const float* __restrict__ s1g, const float* __restrict__ s2g,
    const float* __restrict__ w1, const float* __restrict__ w2,
    const float* __restrict__ w3, const float* __restrict__ w4,
    const float* __restrict__ w5, const float* __restrict__ w6,
    const float* __restrict__ w7, const float* __restrict__ w8,
    float* __restrict__ out)
{
    extern __shared__ float sm[];
    const int b   = blockIdx.x;   // batch 0..255
    const int dir = blockIdx.y;   // 0=fwd (d 0..99), 1=bwd (d 100..199)
    const int tid = threadIdx.x;
    const int dOff = dir * 100;

    float* s1R  = sm + S1O;
    float* s2R  = sm + S2O;
    float* cm   = sm + CMO;
    float* att  = sm + ATO;

    // ================= phase 0: load weights (squared) + s1/s2 slices ======
    {
        const float* wf = dir ? w2 : w1;
        const float* wm = dir ? w4 : w3;
        const float* we = dir ? w6 : w5;
        const float* ws = dir ? w8 : w7;
        for (int e = tid; e < 1000; e += 256) {
            float a;
            a = wf[e]; sm[WFO + e] = a * a;
            a = wm[e]; sm[WMO + e] = a * a;
            a = we[e]; sm[WEO + e] = a * a;
            a = ws[e]; sm[WSO + e] = a * a;
        }
        for (int e = tid; e < 10000; e += 256) {
            int i = e / 100, d = e - i * 100;
            size_t g = ((size_t)i * 256 + b) * 200 + dOff + d;
            s1R[i * 101 + d] = s1g[g];
            s2R[i * 101 + d] = s2g[g];
        }
    }
    __syncthreads();

    // ================= phase 1: norms =======================================
    if (tid < 200) {                        // unweighted 1/||.|| for cosm
        int idx = tid % 100;
        const float* base = (tid < 100) ? s1R : s2R;
        float s = 0.f;
        #pragma unroll 4
        for (int d = 0; d < 100; d++) { float v = base[idx * 101 + d]; s = fmaf(v, v, s); }
        sm[(tid < 100 ? R1O : R2O) + idx] = invs(s);
    }
    // maxpool weighted norms: 2000 tasks (1000 for s1, 1000 for s2)
    for (int r = 0; r < 8; r++) {
        int task = tid + 256 * r;
        if (task < 2000) {
            int which = task / 1000;
            int rem = task - which * 1000;
            int idx = rem / 10, p = rem - idx * 10;
            const float* base = which ? s2R : s1R;
            const float* wp = sm + WMO + p * 100;
            float acc = 0.f;
            for (int d = 0; d < 100; d++) {
                float v = base[idx * 101 + d];
                acc = fmaf(v * v, wp[d], acc);
            }
            sm[(which ? R2WO : R1WO) + rem] = invs(acc);
        }
    }
    if (tid < 10) {                         // full's n2: s2[99] weighted norms per p
        const float* wp = sm + WFO + tid * 100;
        float acc = 0.f;
        for (int d = 0; d < 100; d++) {
            float v = s2R[99 * 101 + d];
            acc = fmaf(v * v, wp[d], acc);
        }
        sm[R2FO + tid] = invs(acc);
    }
    __syncthreads();

    const int ty = tid / 25;      // 0..9 (plus junk for tid>=250, guarded)
    const int tx = tid - ty * 25; // 0..24

    // ================= phase 2: cosm GEMM ==================================
    if (tid < 250) {
        float acc[10][4];
        #pragma unroll
        for (int m = 0; m < 10; m++)
            #pragma unroll
            for (int n = 0; n < 4; n++) acc[m][n] = 0.f;
        for (int d = 0; d < 100; d++) {
            float a[10], bv[4];
            #pragma unroll
            for (int m = 0; m < 10; m++) a[m] = s1R[(ty * 10 + m) * 101 + d];
            #pragma unroll
            for (int n = 0; n < 4; n++) bv[n] = s2R[(tx + 25 * n) * 101 + d];
            #pragma unroll
            for (int m = 0; m < 10; m++)
                #pragma unroll
                for (int n = 0; n < 4; n++) acc[m][n] = fmaf(a[m], bv[n], acc[m][n]);
        }
        #pragma unroll
        for (int m = 0; m < 10; m++) {
            int i = ty * 10 + m;
            float r1 = sm[R1O + i];
            #pragma unroll
            for (int n = 0; n < 4; n++) {
                int j = tx + 25 * n;
                cm[i * 101 + j] = acc[m][n] * r1 * sm[R2O + j];
            }
        }
    }
    __syncthreads();

    // ================= phase 3: rowsum + argmax (first-max) ================
    if (tid < 100) {
        float rs = 0.f, best = -1e30f; int bj = 0;
        for (int j = 0; j < 100; j++) {
            float v = cm[tid * 101 + j];
            rs += v;
            if (v > best) { best = v; bj = j; }
        }
        sm[RSO + tid] = rs;
        reinterpret_cast<int*>(sm)[JMO + tid] = bj;
    }
    __syncthreads();

    // ================= phase 4: maxpool — 10 weighted GEMMs ================
    for (int p = 0; p < 10; p++) {
        if (tid < 250) {
            float acc[10][4];
            #pragma unroll
            for (int m = 0; m < 10; m++)
                #pragma unroll
                for (int n = 0; n < 4; n++) acc[m][n] = 0.f;
            const float* wp = sm + WMO + p * 100;
            for (int d = 0; d < 100; d++) {
                float wv = wp[d];
                float a[10], bv[4];
                #pragma unroll
                for (int m = 0; m < 10; m++) a[m] = s1R[(ty * 10 + m) * 101 + d];
                #pragma unroll
                for (int n = 0; n < 4; n++) bv[n] = s2R[(tx + 25 * n) * 101 + d] * wv;
                #pragma unroll
                for (int m = 0; m < 10; m++)
                    #pragma unroll
                    for (int n = 0; n < 4; n++) acc[m][n] = fmaf(a[m], bv[n], acc[m][n]);
            }
            #pragma unroll
            for (int m = 0; m < 10; m++) {
                int i = ty * 10 + m;
                float r1 = sm[R1WO + i * 10 + p];
                float pm = -1e30f;
                #pragma unroll
                for (int n = 0; n < 4; n++) {
                    int j = tx + 25 * n;
                    pm = fmaxf(pm, acc[m][n] * r1 * sm[R2WO + j * 10 + p]);
                }
                sm[MPO + i * 25 + tx] = pm;
            }
        }
        __syncthreads();
        if (tid < 100) {
            float mv = -1e30f;
            #pragma unroll 5
            for (int k = 0; k < 25; k++) mv = fmaxf(mv, sm[MPO + tid * 25 + k]);
            out[((size_t)tid * 256 + b) * 80 + 20 + dir * 10 + p] = mv;
        }
        __syncthreads();
    }

    // ================= phase 5: mean attention GEMM ========================
    // att[i][d] = (sum_j cosm[i][j] * s2[j][d]) / (rowsum[i] + EPS)
    if (tid < 250) {
        float acc[10][4];
        #pragma unroll
        for (int m = 0; m < 10; m++)
            #pragma unroll
            for (int n = 0; n < 4; n++) acc[m][n] = 0.f;
        for (int j = 0; j < 100; j++) {
            float a[10], bv[4];
            #pragma unroll
            for (int m = 0; m < 10; m++) a[m] = cm[(ty * 10 + m) * 101 + j];
            #pragma unroll
            for (int n = 0; n < 4; n++) bv[n] = s2R[j * 101 + tx + 25 * n];
            #pragma unroll
            for (int m = 0; m < 10; m++)
                #pragma unroll
                for (int n = 0; n < 4; n++) acc[m][n] = fmaf(a[m], bv[n], acc[m][n]);
        }
        #pragma unroll
        for (int m = 0; m < 10; m++) {
            int i = ty * 10 + m;
            float rd = 1.0f / (sm[RSO + i] + EPSf);
            #pragma unroll
            for (int n = 0; n < 4; n++) {
                int d = tx + 25 * n;
                att[i * 101 + d] = acc[m][n] * rd;
            }
        }
    }
    __syncthreads();

    // ======== phase 6: features — full, mean-att, and (dir==1) slot4 =======
    for (int r = 0; r < 4; r++) {
        int task = tid + 256 * r;
        if (task < 1000) {
            int i = task / 10, p = task - i * 10;
            const float* wfp = sm + WFO + p * 100;
            const float* wep = sm + WEO + p * 100;
            const float* wsp = sm + WSO + p * 100;
            float numF = 0.f, n1F = 0.f;
            float numE = 0.f, n1E = 0.f, n2E = 0.f;
            float numS = 0.f, n1S = 0.f, n2S = 0.f;
            for (int d = 0; d < 100; d++) {
                float v1 = s1R[i * 101 + d];
                float v2l = s2R[99 * 101 + d];
                float av = att[i * 101 + d];
                float wf2 = wfp[d], we2 = wep[d];
                numF = fmaf(v1 * v2l, wf2, numF);
                n1F  = fmaf(v1 * v1,  wf2, n1F);
                numE = fmaf(v1 * av,  we2, numE);
                n1E  = fmaf(v1 * v1,  we2, n1E);
                n2E  = fmaf(av * av,  we2, n2E);
                if (dir == 1) {
                    float ws2 = wsp[d];
                    numS = fmaf(v1 * av, ws2, numS);
                    n1S  = fmaf(v1 * v1, ws2, n1S);
                    n2S  = fmaf(av * av, ws2, n2S);
                }
            }
            size_t ob = ((size_t)i * 256 + b) * 80 + dir * 10 + p;
            out[ob +  0] = numF * invs(n1F) * sm[R2FO + p];
            out[ob + 40] = numE * invs(n1E) * invs(n2E);
            if (dir == 1)
                out[ob + 60] = numS * invs(n1S) * invs(n2S);
        }
    }
    __syncthreads();

    // ======== phase 7 (dir==0 only): max-att gather + w7 features ==========
    // Reference bug reproduced: att vector = s2[seq=0, batch=jmax, fwd slice]
    if (dir == 0) {
        for (int e = tid; e < 10000; e += 256) {
            int i = e / 100, d = e - i * 100;
            int jm = reinterpret_cast<int*>(sm)[JMO + i];
            att[i * 101 + d] = __ldg(&s2g[(size_t)jm * 200 + d]);
        }
        __syncthreads();
        for (int r = 0; r < 4; r++) {
            int task = tid + 256 * r;
            if (task < 1000) {
                int i = task / 10, p = task - i * 10;
                const float* wsp = sm + WSO + p * 100;
                float num = 0.f, n1 = 0.f, n2 = 0.f;
                for (int d = 0; d < 100; d++) {
                    float v1 = s1R[i * 101 + d];
                    float av = att[i * 101 + d];
                    float ws2 = wsp[d];
                    num = fmaf(v1 * av, ws2, num);
                    n1  = fmaf(v1 * v1, ws2, n1);
                    n2  = fmaf(av * av, ws2, n2);
                }
                out[((size_t)i * 256 + b) * 80 + 60 + p] = num * invs(n1) * invs(n2);
            }
        }
    }
}

extern "C" void kernel_launch(void* const* d_in, const int* in_sizes, int n_in,
                              void* d_out, int out_size) {
    const float* s1 = (const float*)d_in[0];
    const float* s2 = (const float*)d_in[1];
    const float* w1 = (const float*)d_in[2];
    const float* w2 = (const float*)d_in[3];
    const float* w3 = (const float*)d_in[4];
    const float* w4 = (const float*)d_in[5];
    const float* w5 = (const float*)d_in[6];
    const float* w6 = (const float*)d_in[7];
    const float* w7 = (const float*)d_in[8];
    const float* w8 = (const float*)d_in[9];
    float* out = (float*)d_out;

    static bool attr_set = false;
    if (!attr_set) {
        cudaFuncSetAttribute(matching_kernel,
                             cudaFuncAttributeMaxDynamicSharedMemorySize,
                             SMEM_FLOATS * (int)sizeof(float));
        attr_set = true;
    }
    dim3 grid(256, 2);
    matching_kernel<<<grid, 256, SMEM_FLOATS * sizeof(float)>>>(
        s1, s2, w1, w2, w3, w4, w5, w6, w7, w8, out);
}

// round 3
// speedup vs baseline: 1.3194x; 1.3194x over previous
#include <cuda_runtime.h>
#include <math.h>

#define EPSf 1e-6f

// ---- shared memory layout (float offsets), stride 102 rows ----
#define S1O   0        // s1R[i*102+d]   (10200)
#define S2O   10200    // s2R[j*102+d]   (10200)
#define CMO   20400    // cosm[i*102+j]  (10200)
#define ATO   30600    // att[i*102+d]   (10200)
#define WFO   40800    // w_full^2  [p*100+d] (1000)
#define WMO   41800    // w_maxpool^2
#define WEO   42800    // w_mean^2
#define WSO   43800    // w_slot4^2 (w7 fwd / w8 bwd)
#define R1WO  44800    // 1/n1w maxpool [i*10+p] (1000)
#define R2WO  45800    // 1/n2w maxpool [j*10+p] (1000)
#define R1O   46800    // 1/||s1_i||  (100)
#define R2O   46900    // 1/||s2_j||  (100)
#define RSO   47000    // rowsum of cosm per i (100)
#define JMO   47100    // argmax j per i (int) (100)
#define R2FO  47200    // 1/||s2_last * w_full_p|| per p (16)
#define MPO   47216    // maxpool partial max scratch [i*25+tx] (2500)
#define SMEM_FLOATS 49716

__device__ __forceinline__ float invs(float x) {
    return 1.0f / sqrtf(fmaxf(x, EPSf));
}

// packed fp32x2 FMA / MUL (sm_100+)
__device__ __forceinline__ float2 ffma2(float2 a, float2 b, float2 c) {
    unsigned long long ua = *reinterpret_cast<unsigned long long*>(&a);
    unsigned long long ub = *reinterpret_cast<unsigned long long*>(&b);
    unsigned long long uc = *reinterpret_cast<unsigned long long*>(&c);
    unsigned long long ud;
    asm("fma.rn.f32x2 %0, %1, %2, %3;" : "=l"(ud) : "l"(ua), "l"(ub), "l"(uc));
    return *reinterpret_cast<float2*>(&ud);
}
__device__ __forceinline__ float2 fmul2(float2 a, float2 b) {
    unsigned long long ua = *reinterpret_cast<unsigned long long*>(&a);
    unsigned long long ub = *reinterpret_cast<unsigned long long*>(&b);
    unsigned long long ud;
    asm("mul.rn.f32x2 %0, %1, %2;" : "=l"(ud) : "l"(ua), "l"(ub));
    return *reinterpret_cast<float2*>(&ud);
}

__global__ __launch_bounds__(256, 1) void matching_kernel(
    const float* __restrict__ s1g, const float* __restrict__ s2g,
    const float* __restrict__ w1, const float* __restrict__ w2,
    const float* __restrict__ w3, const float* __restrict__ w4,
    const float* __restrict__ w5, const float* __restrict__ w6,
    const float* __restrict__ w7, const float* __restrict__ w8,
    float* __restrict__ out)
{
    extern __shared__ float sm[];
    const int b   = blockIdx.x;   // batch 0..255
    const int dir = blockIdx.y;   // 0=fwd (d 0..99), 1=bwd (d 100..199)
    const int tid = threadIdx.x;
    const int dOff = dir * 100;

    float* s1R  = sm + S1O;
    float* s2R  = sm + S2O;
    float* cm   = sm + CMO;
    float* att  = sm + ATO;

    // ================= phase 0: load weights (squared) + s1/s2 slices ======
    {
        const float* wf = dir ? w2 : w1;
        const float* wm = dir ? w4 : w3;
        const float* we = dir ? w6 : w5;
        const float* ws = dir ? w8 : w7;
        for (int e = tid; e < 1000; e += 256) {
            float a;
            a = wf[e]; sm[WFO + e] = a * a;
            a = wm[e]; sm[WMO + e] = a * a;
            a = we[e]; sm[WEO + e] = a * a;
            a = ws[e]; sm[WSO + e] = a * a;
        }
        for (int e = tid; e < 10000; e += 256) {
            int i = e / 100, d = e - i * 100;
            size_t g = ((size_t)i * 256 + b) * 200 + dOff + d;
            s1R[i * 102 + d] = s1g[g];
            s2R[i * 102 + d] = s2g[g];
        }
    }
    __syncthreads();

    // ================= phase 1: norms =======================================
    if (tid < 200) {                        // unweighted 1/||.|| for cosm
        int idx = tid % 100;
        const float* base = (tid < 100) ? s1R : s2R;
        float s = 0.f;
        #pragma unroll 4
        for (int d = 0; d < 100; d++) { float v = base[idx * 102 + d]; s = fmaf(v, v, s); }
        sm[(tid < 100 ? R1O : R2O) + idx] = invs(s);
    }
    // maxpool weighted norms: 2000 tasks (1000 for s1, 1000 for s2)
    for (int r = 0; r < 8; r++) {
        int task = tid + 256 * r;
        if (task < 2000) {
            int which = task / 1000;
            int rem = task - which * 1000;
            int idx = rem / 10, p = rem - idx * 10;
            const float* base = which ? s2R : s1R;
            const float* wp = sm + WMO + p * 100;
            float acc = 0.f;
            #pragma unroll 4
            for (int d = 0; d < 100; d++) {
                float v = base[idx * 102 + d];
                acc = fmaf(v * v, wp[d], acc);
            }
            sm[(which ? R2WO : R1WO) + rem] = invs(acc);
        }
    }
    if (tid < 10) {                         // full's n2: s2[99] weighted norms per p
        const float* wp = sm + WFO + tid * 100;
        float acc = 0.f;
        for (int d = 0; d < 100; d++) {
            float v = s2R[99 * 102 + d];
            acc = fmaf(v * v, wp[d], acc);
        }
        sm[R2FO + tid] = invs(acc);
    }
    __syncthreads();

    const int ty = tid / 25;      // 0..9 for tid<250
    const int tx = tid - ty * 25; // 0..24

    // ================= phase 2: cosm GEMM (packed f32x2 over d) ============
    if (tid < 250) {
        float2 acc[10][4];
        #pragma unroll
        for (int m = 0; m < 10; m++)
            #pragma unroll
            for (int n = 0; n < 4; n++) acc[m][n] = make_float2(0.f, 0.f);
        #pragma unroll 2
        for (int d = 0; d < 100; d += 2) {
            float2 a[10], bv[4];
            #pragma unroll
            for (int m = 0; m < 10; m++)
                a[m] = *(const float2*)&s1R[(ty * 10 + m) * 102 + d];
            #pragma unroll
            for (int n = 0; n < 4; n++)
                bv[n] = *(const float2*)&s2R[(tx + 25 * n) * 102 + d];
            #pragma unroll
            for (int m = 0; m < 10; m++)
                #pragma unroll
                for (int n = 0; n < 4; n++) acc[m][n] = ffma2(a[m], bv[n], acc[m][n]);
        }
        #pragma unroll
        for (int m = 0; m < 10; m++) {
            int i = ty * 10 + m;
            float r1 = sm[R1O + i];
            #pragma unroll
            for (int n = 0; n < 4; n++) {
                int j = tx + 25 * n;
                cm[i * 102 + j] = (acc[m][n].x + acc[m][n].y) * r1 * sm[R2O + j];
            }
        }
    }
    __syncthreads();

    // ================= phase 3: rowsum + argmax (first-max) ================
    if (tid < 100) {
        float rs = 0.f, best = -1e30f; int bj = 0;
        for (int j = 0; j < 100; j++) {
            float v = cm[tid * 102 + j];
            rs += v;
            if (v > best) { best = v; bj = j; }
        }
        sm[RSO + tid] = rs;
        reinterpret_cast<int*>(sm)[JMO + tid] = bj;
    }
    __syncthreads();

    // ================= phase 4: maxpool — 10 weighted GEMMs (packed) =======
    for (int p = 0; p < 10; p++) {
        if (tid < 250) {
            float2 acc[10][4];
            #pragma unroll
            for (int m = 0; m < 10; m++)
                #pragma unroll
                for (int n = 0; n < 4; n++) acc[m][n] = make_float2(0.f, 0.f);
            const float* wp = sm + WMO + p * 100;
            #pragma unroll 2
            for (int d = 0; d < 100; d += 2) {
                float2 wv = *(const float2*)&wp[d];
                float2 a[10], bv[4];
                #pragma unroll
                for (int m = 0; m < 10; m++)
                    a[m] = *(const float2*)&s1R[(ty * 10 + m) * 102 + d];
                #pragma unroll
                for (int n = 0; n < 4; n++)
                    bv[n] = fmul2(*(const float2*)&s2R[(tx + 25 * n) * 102 + d], wv);
                #pragma unroll
                for (int m = 0; m < 10; m++)
                    #pragma unroll
                    for (int n = 0; n < 4; n++) acc[m][n] = ffma2(a[m], bv[n], acc[m][n]);
            }
            #pragma unroll
            for (int m = 0; m < 10; m++) {
                int i = ty * 10 + m;
                float r1 = sm[R1WO + i * 10 + p];
                float pm = -1e30f;
                #pragma unroll
                for (int n = 0; n < 4; n++) {
                    int j = tx + 25 * n;
                    pm = fmaxf(pm, (acc[m][n].x + acc[m][n].y) * r1 * sm[R2WO + j * 10 + p]);
                }
                sm[MPO + i * 25 + tx] = pm;
            }
        }
        __syncthreads();
        if (tid < 100) {
            float mv = -1e30f;
            #pragma unroll 5
            for (int k = 0; k < 25; k++) mv = fmaxf(mv, sm[MPO + tid * 25 + k]);
            out[((size_t)tid * 256 + b) * 80 + 20 + dir * 10 + p] = mv;
        }
        __syncthreads();
    }

    // ================= phase 5: mean attention GEMM (scalar) ===============
    // att[i][d] = (sum_j cosm[i][j] * s2[j][d]) / (rowsum[i] + EPS)
    if (tid < 250) {
        float acc[10][4];
        #pragma unroll
        for (int m = 0; m < 10; m++)
            #pragma unroll
            for (int n = 0; n < 4; n++) acc[m][n] = 0.f;
        #pragma unroll 2
        for (int j = 0; j < 100; j++) {
            float a[10], bv[4];
            #pragma unroll
            for (int m = 0; m < 10; m++) a[m] = cm[(ty * 10 + m) * 102 + j];
            #pragma unroll
            for (int n = 0; n < 4; n++) bv[n] = s2R[j * 102 + tx + 25 * n];
            #pragma unroll
            for (int m = 0; m < 10; m++)
                #pragma unroll
                for (int n = 0; n < 4; n++) acc[m][n] = fmaf(a[m], bv[n], acc[m][n]);
        }
        #pragma unroll
        for (int m = 0; m < 10; m++) {
            int i = ty * 10 + m;
            float rd = 1.0f / (sm[RSO + i] + EPSf);
            #pragma unroll
            for (int n = 0; n < 4; n++) {
                int d = tx + 25 * n;
                att[i * 102 + d] = acc[m][n] * rd;
            }
        }
    }
    __syncthreads();

    // ======== phase 6: features — full, mean-att, and (dir==1) slot4 =======
    for (int r = 0; r < 4; r++) {
        int task = tid + 256 * r;
        if (task < 1000) {
            int i = task / 10, p = task - i * 10;
            const float* wfp = sm + WFO + p * 100;
            const float* wep = sm + WEO + p * 100;
            const float* wsp = sm + WSO + p * 100;
            float numF = 0.f, n1F = 0.f;
            float numE = 0.f, n1E = 0.f, n2E = 0.f;
            float numS = 0.f, n1S = 0.f, n2S = 0.f;
            for (int d = 0; d < 100; d++) {
                float v1 = s1R[i * 102 + d];
                float v2l = s2R[99 * 102 + d];
                float av = att[i * 102 + d];
                float wf2 = wfp[d], we2 = wep[d];
                numF = fmaf(v1 * v2l, wf2, numF);
                n1F  = fmaf(v1 * v1,  wf2, n1F);
                numE = fmaf(v1 * av,  we2, numE);
                n1E  = fmaf(v1 * v1,  we2, n1E);
                n2E  = fmaf(av * av,  we2, n2E);
                if (dir == 1) {
                    float ws2 = wsp[d];
                    numS = fmaf(v1 * av, ws2, numS);
                    n1S  = fmaf(v1 * v1, ws2, n1S);
                    n2S  = fmaf(av * av, ws2, n2S);
                }
            }
            size_t ob = ((size_t)i * 256 + b) * 80 + dir * 10 + p;
            out[ob +  0] = numF * invs(n1F) * sm[R2FO + p];
            out[ob + 40] = numE * invs(n1E) * invs(n2E);
            if (dir == 1)
                out[ob + 60] = numS * invs(n1S) * invs(n2S);
        }
    }
    __syncthreads();

    // ======== phase 7 (dir==0 only): max-att gather + w7 features ==========
    // Reference bug reproduced: att vector = s2[seq=0, batch=jmax, fwd slice]
    if (dir == 0) {
        for (int e = tid; e < 10000; e += 256) {
            int i = e / 100, d = e - i * 100;
            int jm = reinterpret_cast<int*>(sm)[JMO + i];
            att[i * 102 + d] = __ldg(&s2g[(size_t)jm * 200 + d]);
        }
        __syncthreads();
        for (int r = 0; r < 4; r++) {
            int task = tid + 256 * r;
            if (task < 1000) {
                int i = task / 10, p = task - i * 10;
                const float* wsp = sm + WSO + p * 100;
                float num = 0.f, n1 = 0.f, n2 = 0.f;
                for (int d = 0; d < 100; d++) {
                    float v1 = s1R[i * 102 + d];
                    float av = att[i * 102 + d];
                    float ws2 = wsp[d];
                    num = fmaf(v1 * av, ws2, num);
                    n1  = fmaf(v1 * v1, ws2, n1);
                    n2  = fmaf(av * av, ws2, n2);
                }
                out[((size_t)i * 256 + b) * 80 + 60 + p] = num * invs(n1) * invs(n2);
            }
        }
    }
}

extern "C" void kernel_launch(void* const* d_in, const int* in_sizes, int n_in,
                              void* d_out, int out_size) {
    const float* s1 = (const float*)d_in[0];
    const float* s2 = (const float*)d_in[1];
    const float* w1 = (const float*)d_in[2];
    const float* w2 = (const float*)d_in[3];
    const float* w3 = (const float*)d_in[4];
    const float* w4 = (const float*)d_in[5];
    const float* w5 = (const float*)d_in[6];
    const float* w6 = (const float*)d_in[7];
    const float* w7 = (const float*)d_in[8];
    const float* w8 = (const float*)d_in[9];
    float* out = (float*)d_out;

    static bool attr_set = false;
    if (!attr_set) {
        cudaFuncSetAttribute(matching_kernel,
                             cudaFuncAttributeMaxDynamicSharedMemorySize,
                             SMEM_FLOATS * (int)sizeof(float));
        attr_set = true;
    }
    dim3 grid(256, 2);
    matching_kernel<<<grid, 256, SMEM_FLOATS * sizeof(float)>>>(
        s1, s2, w1, w2, w3, w4, w5, w6, w7, w8, out);
}

// round 4
// speedup vs baseline: 1.3340x; 1.0110x over previous
#include <cuda_runtime.h>
#include <math.h>

#define EPSf 1e-6f

// ---- shared memory layout (float offsets), stride 102 rows ----
#define S1O   0        // s1R[i*102+d]   (10200)
#define S2O   10200    // s2R[j*102+d]   (10200)
#define CMO   20400    // cosm[i*102+j]  (10200)
#define ATO   30600    // att[i*102+d]   (10200)
#define WFO   40800    // w_full^2  [p*100+d] (1000)
#define WMO   41800    // w_maxpool^2
#define WEO   42800    // w_mean^2
#define WSO   43800    // w_slot4^2 (w7 fwd / w8 bwd)
#define R1WO  44800    // 1/n1w maxpool [i*10+p] (1000)
#define R2WO  45800    // 1/n2w maxpool [j*10+p] (1000)
#define R1O   46800    // 1/||s1_i||  (100)
#define R2O   46900    // 1/||s2_j||  (100)
#define RSO   47000    // rowsum of cosm per i (100)
#define JMO   47100    // argmax j per i (int) (100)
#define R2FO  47200    // 1/||s2_last * w_full_p|| per p (16)
#define MPO   47216    // maxpool partial max scratch, 2 groups [grp*2500 + i*25+tx] (5000)
#define SMEM_FLOATS 52216

__device__ __forceinline__ float invs(float x) {
    return 1.0f / sqrtf(fmaxf(x, EPSf));
}

// packed fp32x2 FMA / MUL (sm_100+)
__device__ __forceinline__ float2 ffma2(float2 a, float2 b, float2 c) {
    unsigned long long ua = *reinterpret_cast<unsigned long long*>(&a);
    unsigned long long ub = *reinterpret_cast<unsigned long long*>(&b);
    unsigned long long uc = *reinterpret_cast<unsigned long long*>(&c);
    unsigned long long ud;
    asm("fma.rn.f32x2 %0, %1, %2, %3;" : "=l"(ud) : "l"(ua), "l"(ub), "l"(uc));
    return *reinterpret_cast<float2*>(&ud);
}
__device__ __forceinline__ float2 fmul2(float2 a, float2 b) {
    unsigned long long ua = *reinterpret_cast<unsigned long long*>(&a);
    unsigned long long ub = *reinterpret_cast<unsigned long long*>(&b);
    unsigned long long ud;
    asm("mul.rn.f32x2 %0, %1, %2;" : "=l"(ud) : "l"(ua), "l"(ub));
    return *reinterpret_cast<float2*>(&ud);
}

__global__ __launch_bounds__(512, 1) void matching_kernel(
    const float* __restrict__ s1g, const float* __restrict__ s2g,
    const float* __restrict__ w1, const float* __restrict__ w2,
    const float* __restrict__ w3, const float* __restrict__ w4,
    const float* __restrict__ w5, const float* __restrict__ w6,
    const float* __restrict__ w7, const float* __restrict__ w8,
    float* __restrict__ out)
{
    extern __shared__ float sm[];
    const int b   = blockIdx.x;   // batch 0..255
    const int dir = blockIdx.y;   // 0=fwd (d 0..99), 1=bwd (d 100..199)
    const int tid = threadIdx.x;
    const int dOff = dir * 100;

    float* s1R  = sm + S1O;
    float* s2R  = sm + S2O;
    float* cm   = sm + CMO;
    float* att  = sm + ATO;

    // ================= phase 0: load weights (squared) + s1/s2 slices ======
    {
        const float* wf = dir ? w2 : w1;
        const float* wm = dir ? w4 : w3;
        const float* we = dir ? w6 : w5;
        const float* ws = dir ? w8 : w7;
        for (int e = tid; e < 1000; e += 512) {
            float a;
            a = wf[e]; sm[WFO + e] = a * a;
            a = wm[e]; sm[WMO + e] = a * a;
            a = we[e]; sm[WEO + e] = a * a;
            a = ws[e]; sm[WSO + e] = a * a;
        }
        for (int e = tid; e < 10000; e += 512) {
            int i = e / 100, d = e - i * 100;
            size_t g = ((size_t)i * 256 + b) * 200 + dOff + d;
            s1R[i * 102 + d] = s1g[g];
            s2R[i * 102 + d] = s2g[g];
        }
    }
    __syncthreads();

    // ================= phase 1: norms =======================================
    if (tid < 200) {                        // unweighted 1/||.|| for cosm
        int idx = tid % 100;
        const float* base = (tid < 100) ? s1R : s2R;
        float s = 0.f;
        #pragma unroll 4
        for (int d = 0; d < 100; d++) { float v = base[idx * 102 + d]; s = fmaf(v, v, s); }
        sm[(tid < 100 ? R1O : R2O) + idx] = invs(s);
    }
    // maxpool weighted norms: 2000 tasks (1000 for s1, 1000 for s2)
    for (int r = 0; r < 4; r++) {
        int task = tid + 512 * r;
        if (task < 2000) {
            int which = task / 1000;
            int rem = task - which * 1000;
            int idx = rem / 10, p = rem - idx * 10;
            const float* base = which ? s2R : s1R;
            const float* wp = sm + WMO + p * 100;
            float acc = 0.f;
            #pragma unroll 4
            for (int d = 0; d < 100; d++) {
                float v = base[idx * 102 + d];
                acc = fmaf(v * v, wp[d], acc);
            }
            sm[(which ? R2WO : R1WO) + rem] = invs(acc);
        }
    }
    if (tid < 10) {                         // full's n2: s2[99] weighted norms per p
        const float* wp = sm + WFO + tid * 100;
        float acc = 0.f;
        for (int d = 0; d < 100; d++) {
            float v = s2R[99 * 102 + d];
            acc = fmaf(v * v, wp[d], acc);
        }
        sm[R2FO + tid] = invs(acc);
    }
    __syncthreads();

    // ================= phase 2: cosm GEMM (packed f32x2 over d) ============
    // 500 threads, tile 5 i x 4 j
    {
        const int ty = tid / 25;       // 0..19
        const int tx = tid - ty * 25;  // 0..24
        if (tid < 500) {
            float2 acc[5][4];
            #pragma unroll
            for (int m = 0; m < 5; m++)
                #pragma unroll
                for (int n = 0; n < 4; n++) acc[m][n] = make_float2(0.f, 0.f);
            for (int d = 0; d < 100; d += 2) {
                float2 a[5];
                #pragma unroll
                for (int m = 0; m < 5; m++)
                    a[m] = *(const float2*)&s1R[(ty * 5 + m) * 102 + d];
                #pragma unroll
                for (int n = 0; n < 4; n++) {
                    float2 bv = *(const float2*)&s2R[(tx + 25 * n) * 102 + d];
                    #pragma unroll
                    for (int m = 0; m < 5; m++) acc[m][n] = ffma2(a[m], bv, acc[m][n]);
                }
            }
            #pragma unroll
            for (int m = 0; m < 5; m++) {
                int i = ty * 5 + m;
                float r1 = sm[R1O + i];
                #pragma unroll
                for (int n = 0; n < 4; n++) {
                    int j = tx + 25 * n;
                    cm[i * 102 + j] = (acc[m][n].x + acc[m][n].y) * r1 * sm[R2O + j];
                }
            }
        }
    }
    __syncthreads();

    // ================= phase 3: rowsum + argmax (first-max) ================
    if (tid < 100) {
        float rs = 0.f, best = -1e30f; int bj = 0;
        for (int j = 0; j < 100; j++) {
            float v = cm[tid * 102 + j];
            rs += v;
            if (v > best) { best = v; bj = j; }
        }
        sm[RSO + tid] = rs;
        reinterpret_cast<int*>(sm)[JMO + tid] = bj;
    }
    __syncthreads();

    // ====== phase 4: maxpool — 10 weighted GEMMs, 2 groups x 5 p each ======
    {
        const int grp = tid / 250;         // 0 or 1 (tid>=500 idle)
        const int t   = tid - grp * 250;   // 0..249
        const int ty  = t / 25;            // 0..9
        const int tx  = t - ty * 25;       // 0..24
        for (int pi = 0; pi < 5; pi++) {
            if (tid < 500) {
                const int p = grp * 5 + pi;
                float2 acc[10][4];
                #pragma unroll
                for (int m = 0; m < 10; m++)
                    #pragma unroll
                    for (int n = 0; n < 4; n++) acc[m][n] = make_float2(0.f, 0.f);
                const float* wp = sm + WMO + p * 100;
                for (int d = 0; d < 100; d += 2) {
                    float2 wv = *(const float2*)&wp[d];
                    float2 a[10];
                    #pragma unroll
                    for (int m = 0; m < 10; m++)
                        a[m] = *(const float2*)&s1R[(ty * 10 + m) * 102 + d];
                    #pragma unroll
                    for (int n = 0; n < 4; n++) {
                        float2 bv = fmul2(*(const float2*)&s2R[(tx + 25 * n) * 102 + d], wv);
                        #pragma unroll
                        for (int m = 0; m < 10; m++) acc[m][n] = ffma2(a[m], bv, acc[m][n]);
                    }
                }
                #pragma unroll
                for (int m = 0; m < 10; m++) {
                    int i = ty * 10 + m;
                    float r1 = sm[R1WO + i * 10 + p];
                    float pm = -1e30f;
                    #pragma unroll
                    for (int n = 0; n < 4; n++) {
                        int j = tx + 25 * n;
                        pm = fmaxf(pm, (acc[m][n].x + acc[m][n].y) * r1 * sm[R2WO + j * 10 + p]);
                    }
                    sm[MPO + grp * 2500 + i * 25 + tx] = pm;
                }
            }
            __syncthreads();
            if (tid < 200) {
                int g = tid / 100, i = tid - g * 100;
                float mv = -1e30f;
                #pragma unroll 5
                for (int k = 0; k < 25; k++)
                    mv = fmaxf(mv, sm[MPO + g * 2500 + i * 25 + k]);
                out[((size_t)i * 256 + b) * 80 + 20 + dir * 10 + (g * 5 + pi)] = mv;
            }
            __syncthreads();
        }
    }

    // ================= phase 5: mean attention GEMM (scalar) ===============
    // att[i][d] = (sum_j cosm[i][j] * s2[j][d]) / (rowsum[i] + EPS)
    {
        const int ty = tid / 25;       // 0..19
        const int tx = tid - ty * 25;  // 0..24
        if (tid < 500) {
            float acc[5][4];
            #pragma unroll
            for (int m = 0; m < 5; m++)
                #pragma unroll
                for (int n = 0; n < 4; n++) acc[m][n] = 0.f;
            #pragma unroll 2
            for (int j = 0; j < 100; j++) {
                float a[5], bv[4];
                #pragma unroll
                for (int m = 0; m < 5; m++) a[m] = cm[(ty * 5 + m) * 102 + j];
                #pragma unroll
                for (int n = 0; n < 4; n++) bv[n] = s2R[j * 102 + tx + 25 * n];
                #pragma unroll
                for (int m = 0; m < 5; m++)
                    #pragma unroll
                    for (int n = 0; n < 4; n++) acc[m][n] = fmaf(a[m], bv[n], acc[m][n]);
            }
            #pragma unroll
            for (int m = 0; m < 5; m++) {
                int i = ty * 5 + m;
                float rd = 1.0f / (sm[RSO + i] + EPSf);
                #pragma unroll
                for (int n = 0; n < 4; n++) {
                    int d = tx + 25 * n;
                    att[i * 102 + d] = acc[m][n] * rd;
                }
            }
        }
    }
    __syncthreads();

    // ======== phase 6: features — full, mean-att, and (dir==1) slot4 =======
    for (int r = 0; r < 2; r++) {
        int task = tid + 512 * r;
        if (task < 1000) {
            int i = task / 10, p = task - i * 10;
            const float* wfp = sm + WFO + p * 100;
            const float* wep = sm + WEO + p * 100;
            const float* wsp = sm + WSO + p * 100;
            float numF = 0.f, n1F = 0.f;
            float numE = 0.f, n1E = 0.f, n2E = 0.f;
            float numS = 0.f, n1S = 0.f, n2S = 0.f;
            for (int d = 0; d < 100; d++) {
                float v1 = s1R[i * 102 + d];
                float v2l = s2R[99 * 102 + d];
                float av = att[i * 102 + d];
                float wf2 = wfp[d], we2 = wep[d];
                numF = fmaf(v1 * v2l, wf2, numF);
                n1F  = fmaf(v1 * v1,  wf2, n1F);
                numE = fmaf(v1 * av,  we2, numE);
                n1E  = fmaf(v1 * v1,  we2, n1E);
                n2E  = fmaf(av * av,  we2, n2E);
                if (dir == 1) {
                    float ws2 = wsp[d];
                    numS = fmaf(v1 * av, ws2, numS);
                    n1S  = fmaf(v1 * v1, ws2, n1S);
                    n2S  = fmaf(av * av, ws2, n2S);
                }
            }
            size_t ob = ((size_t)i * 256 + b) * 80 + dir * 10 + p;
            out[ob +  0] = numF * invs(n1F) * sm[R2FO + p];
            out[ob + 40] = numE * invs(n1E) * invs(n2E);
            if (dir == 1)
                out[ob + 60] = numS * invs(n1S) * invs(n2S);
        }
    }
    __syncthreads();

    // ======== phase 7 (dir==0 only): max-att gather + w7 features ==========
    // Reference bug reproduced: att vector = s2[seq=0, batch=jmax, fwd slice]
    if (dir == 0) {
        for (int e = tid; e < 10000; e += 512) {
            int i = e / 100, d = e - i * 100;
            int jm = reinterpret_cast<int*>(sm)[JMO + i];
            att[i * 102 + d] = __ldg(&s2g[(size_t)jm * 200 + d]);
        }
        __syncthreads();
        for (int r = 0; r < 2; r++) {
            int task = tid + 512 * r;
            if (task < 1000) {
                int i = task / 10, p = task - i * 10;
                const float* wsp = sm + WSO + p * 100;
                float num = 0.f, n1 = 0.f, n2 = 0.f;
                for (int d = 0; d < 100; d++) {
                    float v1 = s1R[i * 102 + d];
                    float av = att[i * 102 + d];
                    float ws2 = wsp[d];
                    num = fmaf(v1 * av, ws2, num);
                    n1  = fmaf(v1 * v1, ws2, n1);
                    n2  = fmaf(av * av, ws2, n2);
                }
                out[((size_t)i * 256 + b) * 80 + 60 + p] = num * invs(n1) * invs(n2);
            }
        }
    }
}

extern "C" void kernel_launch(void* const* d_in, const int* in_sizes, int n_in,
                              void* d_out, int out_size) {
    const float* s1 = (const float*)d_in[0];
    const float* s2 = (const float*)d_in[1];
    const float* w1 = (const float*)d_in[2];
    const float* w2 = (const float*)d_in[3];
    const float* w3 = (const float*)d_in[4];
    const float* w4 = (const float*)d_in[5];
    const float* w5 = (const float*)d_in[6];
    const float* w6 = (const float*)d_in[7];
    const float* w7 = (const float*)d_in[8];
    const float* w8 = (const float*)d_in[9];
    float* out = (float*)d_out;

    static bool attr_set = false;
    if (!attr_set) {
        cudaFuncSetAttribute(matching_kernel,
                             cudaFuncAttributeMaxDynamicSharedMemorySize,
                             SMEM_FLOATS * (int)sizeof(float));
        attr_set = true;
    }
    dim3 grid(256, 2);
    matching_kernel<<<grid, 512, SMEM_FLOATS * sizeof(float)>>>(
        s1, s2, w1, w2, w3, w4, w5, w6, w7, w8, out);
}